// round 10
// baseline (speedup 1.0000x reference)
#include <cuda_runtime.h>
#include <cuda_bf16.h>
#include <cuda_fp16.h>
#include <cstdint>

#define SEQ    256
#define BATCH  32
#define REC    16
#define EMB    32
#define VOCAB  32000
#define NROWS  (SEQ * BATCH)   // 8192
#define VS     10              // vocab splits (k_sum)
#define NPAIR  (VOCAB / 16)    // 2000 column-pairs

// k_out tiling: block = 25-pair slice (smem) x 256 rows (8 warps x 32 rows)
#define OPAIRS 25
#define NCG    (NPAIR / OPAIRS)   // 80 column groups
#define ORPB   256                // rows per block
#define NRG    (NROWS / ORPB)     // 32 row groups

// ---- scratch ----
__device__ float          g_Apre[NROWS * REC];
__device__ __nv_bfloat16  g_hidden[NROWS * REC];
__device__ __nv_bfloat16  g_hiddenL[NROWS * REC];   // hidden * log2(e)
__device__ uint4          g_Vq[NPAIR * 8 * 4];      // permuted V
__device__ float          g_part[VS][NROWS];

__device__ __forceinline__ float ex2f(float x) { float y; asm("ex2.approx.f32 %0, %1;" : "=f"(y) : "f"(x)); return y; }
__device__ __forceinline__ float lg2f(float x) { float y; asm("lg2.approx.f32 %0, %1;" : "=f"(y) : "f"(x)); return y; }
__device__ __forceinline__ float rcpf(float x) { float y; asm("rcp.approx.f32 %0, %1;" : "=f"(y) : "f"(x)); return y; }

#define L2E 1.4426950408889634f
#define LN2 0.6931471805599453f

__device__ __forceinline__ void mma16816(float d[4], const uint32_t a[4], uint32_t b0, uint32_t b1) {
    asm("mma.sync.aligned.m16n8k16.row.col.f32.bf16.bf16.f32 "
        "{%0,%1,%2,%3}, {%4,%5,%6,%7}, {%8,%9}, {%10,%11,%12,%13};"
        : "=f"(d[0]), "=f"(d[1]), "=f"(d[2]), "=f"(d[3])
        : "r"(a[0]), "r"(a[1]), "r"(a[2]), "r"(a[3]),
          "r"(b0), "r"(b1),
          "f"(0.0f), "f"(0.0f), "f"(0.0f), "f"(0.0f));
}

// d = A*B + {nc0,nc0,nc1,nc1}
__device__ __forceinline__ void mma16816c(float d[4], const uint32_t a[4], uint32_t b0, uint32_t b1,
                                          float nc0, float nc1) {
    asm("mma.sync.aligned.m16n8k16.row.col.f32.bf16.bf16.f32 "
        "{%0,%1,%2,%3}, {%4,%5,%6,%7}, {%8,%9}, {%10,%11,%12,%13};"
        : "=f"(d[0]), "=f"(d[1]), "=f"(d[2]), "=f"(d[3])
        : "r"(a[0]), "r"(a[1]), "r"(a[2]), "r"(a[3]),
          "r"(b0), "r"(b1),
          "f"(nc0), "f"(nc0), "f"(nc1), "f"(nc1));
}

__device__ __forceinline__ __half2 h2ex2(float x, float y) {
    uint32_t u, r;
    asm("cvt.rn.f16x2.f32 %0, %1, %2;" : "=r"(u) : "f"(y), "f"(x));
    asm("ex2.approx.f16x2 %0, %1;" : "=r"(r) : "r"(u));
    return *reinterpret_cast<__half2*>(&r);
}

// ---------------- Kernel 1 (prep): V permute + A_pre (vectorized) ----------------
__global__ void k_prep(const int* __restrict__ tok, const float* __restrict__ emb,
                       const float* __restrict__ U, const float* __restrict__ V,
                       const float* __restrict__ b1, const float* __restrict__ b2) {
    int i = blockIdx.x * blockDim.x + threadIdx.x;
    if (i < VOCAB * 8) {
        int c = i >> 3, j = i & 7;
        int t = j & 3, half = j >> 2;
        __nv_bfloat162 p2 = __floats2bfloat162_rn(V[c * REC + 2 * j], V[c * REC + 2 * j + 1]);
        int p    = c >> 4;
        int w16  = c & 15;
        int tile = (w16 >> 1) & 1;
        int n    = ((w16 >> 2) << 1) | (w16 & 1);
        uint32_t* dst = (uint32_t*)g_Vq;
        dst[(((p * 8 + n) * 4 + t) << 2) + tile * 2 + half] = *reinterpret_cast<uint32_t*>(&p2);
    }
    if (i < NROWS * REC) {
        int rid = i >> 4, r = i & 15;
        int tk  = tok[rid];
        const float4* e4 = (const float4*)(emb + (size_t)tk * EMB);
        const float4* u4 = (const float4*)(U + r * EMB);
        float acc = b1[r] + b2[r];
        #pragma unroll
        for (int k = 0; k < EMB / 4; k++) {
            float4 e = e4[k], u = u4[k];
            acc = fmaf(e.x, u.x, acc);
            acc = fmaf(e.y, u.y, acc);
            acc = fmaf(e.z, u.z, acc);
            acc = fmaf(e.w, u.w, acc);
        }
        g_Apre[i] = acc;
    }
}

// ---------------- Kernel 2: serial recurrence ----------------
__global__ void k_rnn(const float* __restrict__ W, const float* __restrict__ h0v) {
    int lane = threadIdx.x;
    int b = blockIdx.x * 2 + (lane >> 4);
    int r = lane & 15;
    float w[REC];
    #pragma unroll
    for (int j = 0; j < REC; j++) w[j] = W[r * REC + j];
    float h = h0v[r];
    g_hidden[b * REC + r]  = __float2bfloat16(h);
    g_hiddenL[b * REC + r] = __float2bfloat16(h * L2E);
    float anext = g_Apre[b * REC + r];
    for (int t = 0; t < SEQ - 1; t++) {
        float a = anext;
        if (t < SEQ - 2) anext = g_Apre[((t + 1) * BATCH + b) * REC + r];
        float s0 = a, s1 = 0.f, s2 = 0.f, s3 = 0.f;
        #pragma unroll
        for (int j = 0; j < REC; j += 4) {
            float h0_ = __shfl_sync(0xffffffffu, h, j,     16);
            float h1_ = __shfl_sync(0xffffffffu, h, j + 1, 16);
            float h2_ = __shfl_sync(0xffffffffu, h, j + 2, 16);
            float h3_ = __shfl_sync(0xffffffffu, h, j + 3, 16);
            s0 = fmaf(h0_, w[j],     s0);
            s1 = fmaf(h1_, w[j + 1], s1);
            s2 = fmaf(h2_, w[j + 2], s2);
            s3 = fmaf(h3_, w[j + 3], s3);
        }
        float z  = ((s0 + s1) + (s2 + s3)) * (2.0f * L2E);
        float ez = ex2f(z);
        h = 1.0f - 2.0f * rcpf(ez + 1.0f);
        int idx = ((t + 1) * BATCH + b) * REC + r;
        g_hidden[idx]  = __float2bfloat16(h);
        g_hiddenL[idx] = __float2bfloat16(h * L2E);
    }
}

// ---------------- Kernel 3 (pass 1): partial sum exp (R5 version) ----------------
// grid (256, VS), 256 thr; warp covers 25 pairs. Flush every 5 pairs.
__global__ void __launch_bounds__(256, 5) k_sum() {
    const int lane = threadIdx.x & 31, warp = threadIdx.x >> 5;
    const int g = lane >> 2, t = lane & 3;
    const int tile  = blockIdx.x * 32;
    const int split = blockIdx.y;

    uint32_t a[2][4];
    const uint32_t* H = (const uint32_t*)g_hiddenL;
    #pragma unroll
    for (int f = 0; f < 2; f++) {
        int r0 = tile + f * 16 + g;
        a[f][0] = H[r0 * 8 + t];
        a[f][1] = H[(r0 + 8) * 8 + t];
        a[f][2] = H[r0 * 8 + t + 4];
        a[f][3] = H[(r0 + 8) * 8 + t + 4];
    }

    float s[2][2];
    __half2 hacc[2][2];
    #pragma unroll
    for (int f = 0; f < 2; f++) {
        s[f][0] = s[f][1] = 0.f;
        hacc[f][0] = hacc[f][1] = __float2half2_rn(0.f);
    }

    const int p0 = split * (NPAIR / VS) + warp * OPAIRS;
    uint4 b = g_Vq[(p0 * 8 + g) * 4 + t];
    #pragma unroll 1
    for (int blk = 0; blk < 5; blk++) {
        #pragma unroll
        for (int q = 0; q < 5; q++) {
            int p = p0 + blk * 5 + q;
            uint4 bn;
            if (blk * 5 + q < 24) bn = g_Vq[((p + 1) * 8 + g) * 4 + t];
            #pragma unroll
            for (int f = 0; f < 2; f++) {
                float d0[4], d1[4];
                mma16816(d0, a[f], b.x, b.y);
                mma16816(d1, a[f], b.z, b.w);
                hacc[f][0] = __hadd2(hacc[f][0], h2ex2(d0[0], d0[1]));
                hacc[f][0] = __hadd2(hacc[f][0], h2ex2(d1[0], d1[1]));
                hacc[f][1] = __hadd2(hacc[f][1], h2ex2(d0[2], d0[3]));
                hacc[f][1] = __hadd2(hacc[f][1], h2ex2(d1[2], d1[3]));
            }
            b = bn;
        }
        #pragma unroll
        for (int f = 0; f < 2; f++) {
            float2 f0 = __half22float2(hacc[f][0]);
            float2 f1 = __half22float2(hacc[f][1]);
            s[f][0] += f0.x + f0.y;
            s[f][1] += f1.x + f1.y;
            hacc[f][0] = hacc[f][1] = __float2half2_rn(0.f);
        }
    }
    #pragma unroll
    for (int f = 0; f < 2; f++)
        #pragma unroll
        for (int m = 1; m <= 2; m <<= 1) {
            s[f][0] += __shfl_xor_sync(0xffffffffu, s[f][0], m);
            s[f][1] += __shfl_xor_sync(0xffffffffu, s[f][1], m);
        }
    __shared__ float red[8][32];
    if (t == 0) {
        #pragma unroll
        for (int f = 0; f < 2; f++) {
            red[warp][f * 16 + g]     = s[f][0];
            red[warp][f * 16 + g + 8] = s[f][1];
        }
    }
    __syncthreads();
    if (threadIdx.x < 32) {
        float tot = 0.f;
        #pragma unroll
        for (int wq = 0; wq < 8; wq++) tot += red[wq][threadIdx.x];
        g_part[split][tile + threadIdx.x] = tot;
    }
}

// ---------------- Kernel 4 (pass 2): smem-staged V slice, 256 rows/block ----------------
// grid (NCG=80, NRG=32); block stages 25 pairs (12.8KB) once, each warp does 32 rows.
__global__ void __launch_bounds__(256, 5) k_out(float* __restrict__ out) {
    __shared__ uint4 sVq[OPAIRS * 32];

    const int lane = threadIdx.x & 31, warp = threadIdx.x >> 5;
    const int g = lane >> 2, t = lane & 3;
    const int cg   = blockIdx.x;              // column group: pairs cg*25 .. +24
    const int rbase = blockIdx.y * ORPB + warp * 32;

    // stage slice: sVq[i] = g_Vq[cg*25*32 + i]
    {
        const uint4* src = g_Vq + cg * (OPAIRS * 32);
        for (int i = threadIdx.x; i < OPAIRS * 32; i += 256) sVq[i] = src[i];
    }

    // A fragments for this warp's 32 rows
    uint32_t a[2][4];
    const uint32_t* H = (const uint32_t*)g_hidden;
    #pragma unroll
    for (int f = 0; f < 2; f++) {
        int r0 = rbase + f * 16 + g;
        a[f][0] = H[r0 * 8 + t];
        a[f][1] = H[(r0 + 8) * 8 + t];
        a[f][2] = H[r0 * 8 + t + 4];
        a[f][3] = H[(r0 + 8) * 8 + t + 4];
    }
    // row log-constants
    float nc[2][2];
    #pragma unroll
    for (int f = 0; f < 2; f++) {
        int r0 = rbase + f * 16 + g;
        float s0 = 0.f, s1 = 0.f;
        #pragma unroll
        for (int q = 0; q < VS; q++) {
            s0 += g_part[q][r0];
            s1 += g_part[q][r0 + 8];
        }
        nc[f][0] = -(LN2 * lg2f(s0));
        nc[f][1] = -(LN2 * lg2f(s1));
    }
    __syncthreads();

    float* base = out + (size_t)(rbase + g) * VOCAB + cg * (OPAIRS * 16) + 4 * t;

    uint4 b = sVq[lane];
    #pragma unroll 1
    for (int pl = 0; pl < OPAIRS; pl++) {
        uint4 bn;
        if (pl + 1 < OPAIRS) bn = sVq[(pl + 1) * 32 + lane];
        float* bp = base + pl * 16;
        #pragma unroll
        for (int f = 0; f < 2; f++) {
            float d0[4], d1[4];
            mma16816c(d0, a[f], b.x, b.y, nc[f][0], nc[f][1]);
            mma16816c(d1, a[f], b.z, b.w, nc[f][0], nc[f][1]);
            __stcs((float4*)(bp + (size_t)(f * 16)     * VOCAB),
                   make_float4(d0[0], d0[1], d1[0], d1[1]));
            __stcs((float4*)(bp + (size_t)(f * 16 + 8) * VOCAB),
                   make_float4(d0[2], d0[3], d1[2], d1[3]));
        }
        b = bn;
    }
}

extern "C" void kernel_launch(void* const* d_in, const int* in_sizes, int n_in,
                              void* d_out, int out_size) {
    const int*   tok = (const int*)d_in[0];
    const float* emb = (const float*)d_in[1];
    const float* U   = (const float*)d_in[2];
    const float* W   = (const float*)d_in[3];
    const float* V   = (const float*)d_in[4];
    const float* b1  = (const float*)d_in[5];
    const float* b2  = (const float*)d_in[6];
    const float* h0  = (const float*)d_in[7];
    float* out = (float*)d_out;

    k_prep<<<(VOCAB * 8 + 255) / 256, 256>>>(tok, emb, U, V, b1, b2);
    k_rnn<<<BATCH / 2, 32>>>(W, h0);
    dim3 gs(NROWS / 32, VS);
    k_sum<<<gs, 256>>>();
    dim3 go(NCG, NRG);
    k_out<<<go, 256>>>(out);
}

// round 11
// speedup vs baseline: 1.0398x; 1.0398x over previous
#include <cuda_runtime.h>
#include <cuda_bf16.h>
#include <cuda_fp16.h>
#include <cstdint>

#define SEQ    256
#define BATCH  32
#define REC    16
#define EMB    32
#define VOCAB  32000
#define NROWS  (SEQ * BATCH)   // 8192
#define NPAIR  (VOCAB / 16)    // 2000 column-pairs

// shared tiling for k_sum / k_out: 25-pair smem slice x 256 rows (8 warps x 32)
#define OPAIRS 25
#define NCG    (NPAIR / OPAIRS)   // 80 column groups
#define ORPB   256
#define NRG    (NROWS / ORPB)     // 32 row groups

// ---- scratch ----
__device__ float          g_Apre[NROWS * REC];      // prescaled by 2*log2(e)
__device__ __nv_bfloat16  g_hidden[NROWS * REC];
__device__ __nv_bfloat16  g_hiddenL[NROWS * REC];   // hidden * log2(e)
__device__ uint4          g_Vq[NPAIR * 8 * 4];      // permuted V
__device__ float          g_part[NCG][NROWS];       // per-colgroup partial sumexp
__device__ float          g_rowc[NROWS];            // -ln(sum)

__device__ __forceinline__ float ex2f(float x) { float y; asm("ex2.approx.f32 %0, %1;" : "=f"(y) : "f"(x)); return y; }
__device__ __forceinline__ float lg2f(float x) { float y; asm("lg2.approx.f32 %0, %1;" : "=f"(y) : "f"(x)); return y; }
__device__ __forceinline__ float rcpf(float x) { float y; asm("rcp.approx.f32 %0, %1;" : "=f"(y) : "f"(x)); return y; }

#define L2E 1.4426950408889634f
#define LN2 0.6931471805599453f

__device__ __forceinline__ void mma16816(float d[4], const uint32_t a[4], uint32_t b0, uint32_t b1) {
    asm("mma.sync.aligned.m16n8k16.row.col.f32.bf16.bf16.f32 "
        "{%0,%1,%2,%3}, {%4,%5,%6,%7}, {%8,%9}, {%10,%11,%12,%13};"
        : "=f"(d[0]), "=f"(d[1]), "=f"(d[2]), "=f"(d[3])
        : "r"(a[0]), "r"(a[1]), "r"(a[2]), "r"(a[3]),
          "r"(b0), "r"(b1),
          "f"(0.0f), "f"(0.0f), "f"(0.0f), "f"(0.0f));
}

__device__ __forceinline__ void mma16816c(float d[4], const uint32_t a[4], uint32_t b0, uint32_t b1,
                                          float nc0, float nc1) {
    asm("mma.sync.aligned.m16n8k16.row.col.f32.bf16.bf16.f32 "
        "{%0,%1,%2,%3}, {%4,%5,%6,%7}, {%8,%9}, {%10,%11,%12,%13};"
        : "=f"(d[0]), "=f"(d[1]), "=f"(d[2]), "=f"(d[3])
        : "r"(a[0]), "r"(a[1]), "r"(a[2]), "r"(a[3]),
          "r"(b0), "r"(b1),
          "f"(nc0), "f"(nc0), "f"(nc1), "f"(nc1));
}

__device__ __forceinline__ __half2 h2ex2(float x, float y) {
    uint32_t u, r;
    asm("cvt.rn.f16x2.f32 %0, %1, %2;" : "=r"(u) : "f"(y), "f"(x));
    asm("ex2.approx.f16x2 %0, %1;" : "=r"(r) : "r"(u));
    return *reinterpret_cast<__half2*>(&r);
}

// ---------------- Kernel 1 (prep): specialized block ranges ----------------
// Blocks [0, 125): V permute, one vocab column per thread.
// Blocks [125, 125+512): A_pre (prescaled by 2*L2E).
#define PREP_VBLK (VOCAB / 256)          // 125
#define PREP_ABLK (NROWS * REC / 256)    // 512
__global__ void k_prep(const int* __restrict__ tok, const float* __restrict__ emb,
                       const float* __restrict__ U, const float* __restrict__ V,
                       const float* __restrict__ b1, const float* __restrict__ b2) {
    if (blockIdx.x < PREP_VBLK) {
        int c = blockIdx.x * 256 + threadIdx.x;       // vocab column
        const float4* v4 = (const float4*)(V + (size_t)c * REC);
        float4 q0 = v4[0], q1 = v4[1], q2 = v4[2], q3 = v4[3];
        float vv[16] = {q0.x,q0.y,q0.z,q0.w, q1.x,q1.y,q1.z,q1.w,
                        q2.x,q2.y,q2.z,q2.w, q3.x,q3.y,q3.z,q3.w};
        uint32_t pk[8];
        #pragma unroll
        for (int j = 0; j < 8; j++) {
            __nv_bfloat162 p2 = __floats2bfloat162_rn(vv[2*j], vv[2*j+1]);
            pk[j] = *reinterpret_cast<uint32_t*>(&p2);
        }
        int p    = c >> 4;
        int w16  = c & 15;
        int tile = (w16 >> 1) & 1;
        int n    = ((w16 >> 2) << 1) | (w16 & 1);
        uint32_t* dst = (uint32_t*)g_Vq;
        #pragma unroll
        for (int t = 0; t < 4; t++) {
            // slots (tile*2, tile*2+1) = (pair j=t [half0], pair j=t+4 [half1])
            uint2 val = make_uint2(pk[t], pk[t + 4]);
            *(uint2*)(dst + ((((p * 8 + n) * 4 + t) << 2) + tile * 2)) = val;
        }
    } else {
        int i = (blockIdx.x - PREP_VBLK) * 256 + threadIdx.x;   // < NROWS*REC
        int rid = i >> 4, r = i & 15;
        int tk  = tok[rid];
        const float4* e4 = (const float4*)(emb + (size_t)tk * EMB);
        const float4* u4 = (const float4*)(U + r * EMB);
        float acc = b1[r] + b2[r];
        #pragma unroll
        for (int k = 0; k < EMB / 4; k++) {
            float4 e = e4[k], u = u4[k];
            acc = fmaf(e.x, u.x, acc);
            acc = fmaf(e.y, u.y, acc);
            acc = fmaf(e.z, u.z, acc);
            acc = fmaf(e.w, u.w, acc);
        }
        g_Apre[i] = acc * (2.0f * L2E);    // prescale for rnn
    }
}

// ---------------- Kernel 2: serial recurrence (scale folded into w,a) --------
__global__ void k_rnn(const float* __restrict__ W, const float* __restrict__ h0v) {
    int lane = threadIdx.x;
    int b = blockIdx.x * 2 + (lane >> 4);
    int r = lane & 15;
    float w[REC];
    #pragma unroll
    for (int j = 0; j < REC; j++) w[j] = W[r * REC + j] * (2.0f * L2E);
    float h = h0v[r];
    g_hidden[b * REC + r]  = __float2bfloat16(h);
    g_hiddenL[b * REC + r] = __float2bfloat16(h * L2E);
    float anext = g_Apre[b * REC + r];
    for (int t = 0; t < SEQ - 1; t++) {
        float a = anext;
        if (t < SEQ - 2) anext = g_Apre[((t + 1) * BATCH + b) * REC + r];
        float s0 = a, s1 = 0.f, s2 = 0.f, s3 = 0.f;
        #pragma unroll
        for (int j = 0; j < REC; j += 4) {
            float h0_ = __shfl_sync(0xffffffffu, h, j,     16);
            float h1_ = __shfl_sync(0xffffffffu, h, j + 1, 16);
            float h2_ = __shfl_sync(0xffffffffu, h, j + 2, 16);
            float h3_ = __shfl_sync(0xffffffffu, h, j + 3, 16);
            s0 = fmaf(h0_, w[j],     s0);
            s1 = fmaf(h1_, w[j + 1], s1);
            s2 = fmaf(h2_, w[j + 2], s2);
            s3 = fmaf(h3_, w[j + 3], s3);
        }
        float z  = (s0 + s1) + (s2 + s3);          // already 2x*log2(e)
        float ez = ex2f(z);
        h = 1.0f - 2.0f * rcpf(ez + 1.0f);
        int idx = ((t + 1) * BATCH + b) * REC + r;
        g_hidden[idx]  = __float2bfloat16(h);
        g_hiddenL[idx] = __float2bfloat16(h * L2E);
    }
}

// ---------------- Kernel 3 (pass 1): smem-staged partial sum exp ----------------
// grid (NCG=80, NRG=32); block stages 25 pairs once, each warp owns 32 rows.
__global__ void __launch_bounds__(256, 5) k_sum() {
    __shared__ uint4 sVq[OPAIRS * 32];

    const int lane = threadIdx.x & 31, warp = threadIdx.x >> 5;
    const int g = lane >> 2, t = lane & 3;
    const int cg    = blockIdx.x;
    const int rbase = blockIdx.y * ORPB + warp * 32;

    {
        const uint4* src = g_Vq + cg * (OPAIRS * 32);
        for (int i = threadIdx.x; i < OPAIRS * 32; i += 256) sVq[i] = src[i];
    }

    uint32_t a[2][4];
    const uint32_t* H = (const uint32_t*)g_hiddenL;
    #pragma unroll
    for (int f = 0; f < 2; f++) {
        int r0 = rbase + f * 16 + g;
        a[f][0] = H[r0 * 8 + t];
        a[f][1] = H[(r0 + 8) * 8 + t];
        a[f][2] = H[r0 * 8 + t + 4];
        a[f][3] = H[(r0 + 8) * 8 + t + 4];
    }
    __syncthreads();

    float s[2][2];
    __half2 hacc[2][2];
    #pragma unroll
    for (int f = 0; f < 2; f++) {
        s[f][0] = s[f][1] = 0.f;
        hacc[f][0] = hacc[f][1] = __float2half2_rn(0.f);
    }

    uint4 b = sVq[lane];
    #pragma unroll 1
    for (int blk = 0; blk < 5; blk++) {           // flush every 5 pairs
        #pragma unroll
        for (int q = 0; q < 5; q++) {
            int pl = blk * 5 + q;
            uint4 bn;
            if (pl + 1 < OPAIRS) bn = sVq[(pl + 1) * 32 + lane];
            #pragma unroll
            for (int f = 0; f < 2; f++) {
                float d0[4], d1[4];
                mma16816(d0, a[f], b.x, b.y);
                mma16816(d1, a[f], b.z, b.w);
                hacc[f][0] = __hadd2(hacc[f][0], h2ex2(d0[0], d0[1]));
                hacc[f][0] = __hadd2(hacc[f][0], h2ex2(d1[0], d1[1]));
                hacc[f][1] = __hadd2(hacc[f][1], h2ex2(d0[2], d0[3]));
                hacc[f][1] = __hadd2(hacc[f][1], h2ex2(d1[2], d1[3]));
            }
            b = bn;
        }
        #pragma unroll
        for (int f = 0; f < 2; f++) {
            float2 f0 = __half22float2(hacc[f][0]);
            float2 f1 = __half22float2(hacc[f][1]);
            s[f][0] += f0.x + f0.y;
            s[f][1] += f1.x + f1.y;
            hacc[f][0] = hacc[f][1] = __float2half2_rn(0.f);
        }
    }
    // reduce across the 4 t-lanes; rows are warp-private, so write directly
    #pragma unroll
    for (int f = 0; f < 2; f++) {
        #pragma unroll
        for (int m = 1; m <= 2; m <<= 1) {
            s[f][0] += __shfl_xor_sync(0xffffffffu, s[f][0], m);
            s[f][1] += __shfl_xor_sync(0xffffffffu, s[f][1], m);
        }
        if (t == 0) {
            int r0 = rbase + f * 16 + g;
            g_part[cg][r0]     = s[f][0];
            g_part[cg][r0 + 8] = s[f][1];
        }
    }
}

// ---------------- Kernel 3.5: collapse partials -> -ln(sum) per row ----------------
__global__ void k_reduce() {
    int row = blockIdx.x * 256 + threadIdx.x;
    float s = 0.f;
    #pragma unroll
    for (int cg = 0; cg < NCG; cg++) s += g_part[cg][row];
    g_rowc[row] = -(LN2 * lg2f(s));
}

// ---------------- Kernel 4 (pass 2): smem-staged out = logit - ln(sum) ----------------
__global__ void __launch_bounds__(256, 5) k_out(float* __restrict__ out) {
    __shared__ uint4 sVq[OPAIRS * 32];

    const int lane = threadIdx.x & 31, warp = threadIdx.x >> 5;
    const int g = lane >> 2, t = lane & 3;
    const int cg    = blockIdx.x;
    const int rbase = blockIdx.y * ORPB + warp * 32;

    {
        const uint4* src = g_Vq + cg * (OPAIRS * 32);
        for (int i = threadIdx.x; i < OPAIRS * 32; i += 256) sVq[i] = src[i];
    }

    uint32_t a[2][4];
    const uint32_t* H = (const uint32_t*)g_hidden;
    float nc[2][2];
    #pragma unroll
    for (int f = 0; f < 2; f++) {
        int r0 = rbase + f * 16 + g;
        a[f][0] = H[r0 * 8 + t];
        a[f][1] = H[(r0 + 8) * 8 + t];
        a[f][2] = H[r0 * 8 + t + 4];
        a[f][3] = H[(r0 + 8) * 8 + t + 4];
        nc[f][0] = g_rowc[r0];
        nc[f][1] = g_rowc[r0 + 8];
    }
    __syncthreads();

    float* base = out + (size_t)(rbase + g) * VOCAB + cg * (OPAIRS * 16) + 4 * t;

    uint4 b = sVq[lane];
    #pragma unroll 1
    for (int pl = 0; pl < OPAIRS; pl++) {
        uint4 bn;
        if (pl + 1 < OPAIRS) bn = sVq[(pl + 1) * 32 + lane];
        float* bp = base + pl * 16;
        #pragma unroll
        for (int f = 0; f < 2; f++) {
            float d0[4], d1[4];
            mma16816c(d0, a[f], b.x, b.y, nc[f][0], nc[f][1]);
            mma16816c(d1, a[f], b.z, b.w, nc[f][0], nc[f][1]);
            __stcs((float4*)(bp + (size_t)(f * 16)     * VOCAB),
                   make_float4(d0[0], d0[1], d1[0], d1[1]));
            __stcs((float4*)(bp + (size_t)(f * 16 + 8) * VOCAB),
                   make_float4(d0[2], d0[3], d1[2], d1[3]));
        }
        b = bn;
    }
}

extern "C" void kernel_launch(void* const* d_in, const int* in_sizes, int n_in,
                              void* d_out, int out_size) {
    const int*   tok = (const int*)d_in[0];
    const float* emb = (const float*)d_in[1];
    const float* U   = (const float*)d_in[2];
    const float* W   = (const float*)d_in[3];
    const float* V   = (const float*)d_in[4];
    const float* b1  = (const float*)d_in[5];
    const float* b2  = (const float*)d_in[6];
    const float* h0  = (const float*)d_in[7];
    float* out = (float*)d_out;

    k_prep<<<PREP_VBLK + PREP_ABLK, 256>>>(tok, emb, U, V, b1, b2);
    k_rnn<<<BATCH / 2, 32>>>(W, h0);
    dim3 gs(NCG, NRG);
    k_sum<<<gs, 256>>>();
    k_reduce<<<NROWS / 256, 256>>>();
    k_out<<<gs, 256>>>(out);
}